// round 16
// baseline (speedup 1.0000x reference)
#include <cuda_runtime.h>
#include <cuda_bf16.h>
#include <mma.h>
#include <math.h>

#define B_     64
#define NSIDE  40
#define NPTS   1600
#define S_     512
#define C1_    20
#define W_     128
#define SCN    10240
#define GSPLIT 16
#define ZSPLIT 86

typedef unsigned long long u64;

// ---------------- scratch (device globals; no runtime allocation) ----------------
__device__ __align__(16) __nv_bfloat16 g_f1hi[SCN * NPTS];
__device__ __align__(16) __nv_bfloat16 g_f1lo[SCN * NPTS];
__device__ __align__(16) __nv_bfloat16 g_dhi [B_ * NPTS];
__device__ __align__(16) __nv_bfloat16 g_dlo [B_ * NPTS];
__device__ __align__(16) float g_z1  [SCN * B_];
__device__ __align__(16) float g_h2  [S_ * W_];
__device__ __align__(16) float g_G   [129 * 1280];
__device__ __align__(16) float g_z2  [B_ * W_];

// ---------------- f32x2 helpers ---------------------------------------------------
__device__ __forceinline__ u64 pk2(float lo, float hi) {
    u64 r;
    asm("mov.b64 %0, {%1, %2};" : "=l"(r) : "f"(lo), "f"(hi));
    return r;
}
__device__ __forceinline__ void upk2(u64 v, float& lo, float& hi) {
    asm("mov.b64 {%0, %1}, %2;" : "=f"(lo), "=f"(hi) : "l"(v));
}
__device__ __forceinline__ void fma2p(u64& d, u64 a, u64 b) {
    asm("fma.rn.f32x2 %0, %1, %2, %0;" : "+l"(d) : "l"(a), "l"(b));
}

__device__ __forceinline__ float silu_f(float x) { return x / (1.0f + __expf(-x)); }
__device__ __forceinline__ float silu_t(float x) {
    float t;
    asm("tanh.approx.f32 %0, %1;" : "=f"(t) : "f"(0.5f * x));
    return 0.5f * x * (1.0f + t);
}

// ---------------- K0: zero atomic accumulators ------------------------------------
__global__ __launch_bounds__(256) void kzero()
{
    int i = blockIdx.x * 256 + threadIdx.x;
    float4 z = make_float4(0.f, 0.f, 0.f, 0.f);
    if (i < 129 * 1280 / 4) ((float4*)g_G)[i] = z;
    if (i < B_ * W_ / 4)    ((float4*)g_z2)[i] = z;
}

// ---------------- Kdata: split data into bf16 hi/lo -------------------------------
__global__ __launch_bounds__(256) void kdata(const float* __restrict__ data)
{
    int i = blockIdx.x * 256 + threadIdx.x;
    if (i < B_ * NPTS) {
        float v = data[i];
        __nv_bfloat16 h = __float2bfloat16(v);
        g_dhi[i] = h;
        g_dlo[i] = __float2bfloat16(v - __bfloat162float(h));
    }
}

// ---------------- K1: filt1 hi/lo bf16 = MLP(embed(projective coords)) ------------
#define BP 264

__device__ __forceinline__ void k1_layer(const float* in, float* out,
                                         const float* w, const float* bias,
                                         int og, int pl)
{
    int ob = og * 10;
    u64 acc[4][5];
#pragma unroll
    for (int ip = 0; ip < 4; ip++)
#pragma unroll
        for (int j = 0; j < 5; j++)
            acc[ip][j] = pk2(bias[ob + 2*j], bias[ob + 2*j + 1]);
#pragma unroll 4
    for (int i = 0; i < 20; i++) {
        u64 wv[5];
#pragma unroll
        for (int j = 0; j < 5; j++)
            wv[j] = *(const u64*)&w[i * 20 + ob + 2 * j];
#pragma unroll
        for (int ip = 0; ip < 4; ip++) {
            float e = in[i * BP + pl + 64 * ip];
            u64 ed = pk2(e, e);
#pragma unroll
            for (int j = 0; j < 5; j++) fma2p(acc[ip][j], ed, wv[j]);
        }
    }
#pragma unroll
    for (int ip = 0; ip < 4; ip++)
#pragma unroll
        for (int j = 0; j < 5; j++) {
            float a0, a1;
            upk2(acc[ip][j], a0, a1);
            out[(ob + 2*j)     * BP + pl + 64 * ip] = silu_t(a0);
            out[(ob + 2*j + 1) * BP + pl + 64 * ip] = silu_t(a1);
        }
}

__global__ __launch_bounds__(128) void k1_filt1(
    const float* __restrict__ v_last,
    const float* __restrict__ fw1, const float* __restrict__ fb1,
    const float* __restrict__ fw2, const float* __restrict__ fb2,
    const float* __restrict__ fw3, const float* __restrict__ fb3)
{
    __shared__ __align__(16) float sw1[400], sw2[400], sw3[400];
    __shared__ float sb1[20], sb2[20], sb3[20];
    __shared__ __align__(16) float bufA[20 * BP], bufB[20 * BP];

    int s   = blockIdx.y;
    int n0  = blockIdx.x * 256;
    int tid = threadIdx.x;

    for (int i = tid; i < 400; i += 128) {
        sw1[i] = fw1[i];
        sw2[i] = fw2[i];
        sw3[i] = fw3[i];
    }
    if (tid < 20) {
        sb1[tid] = fb1[tid];
        sb2[tid] = fb2[tid];
        sb3[tid] = fb3[tid];
    }

    float v[8];
#pragma unroll
    for (int i = 0; i < 8; i++) v[i] = 0.1f * __ldg(&v_last[s * 8 + i]);

#pragma unroll
    for (int q = 0; q < 2; q++) {
        int p = tid + q * 128;
        int n = n0 + p;
        int ic = n / NSIDE, jc = n - ic * NSIDE;
        float x = -1.0f + (2.0f / 39.0f) * (float)ic;
        float y = -1.0f + (2.0f / 39.0f) * (float)jc;
        float y0 = (1.0f + v[0]) * x + v[1] * y + v[2];
        float y1 = v[3] * x + (1.0f + v[4]) * y + v[5];
        float y2 = v[6] * x + v[7] * y + 1.0f;
        float inv = __frcp_rn(y2);
        float t0 = y0 * inv, t1 = y1 * inv;

        float sa, ca;
        __sincosf(t0, &sa, &ca);
        bufA[0 * BP + p] = sa;
        bufA[5 * BP + p] = ca;
#pragma unroll
        for (int k = 1; k < 5; k++) {
            float s2 = 2.0f * sa * ca;
            float c2 = 2.0f * ca * ca - 1.0f;
            bufA[k * BP + p] = s2;
            bufA[(5 + k) * BP + p] = c2;
            sa = s2; ca = c2;
        }
        __sincosf(t1, &sa, &ca);
        bufA[10 * BP + p] = sa;
        bufA[15 * BP + p] = ca;
#pragma unroll
        for (int k = 1; k < 5; k++) {
            float s2 = 2.0f * sa * ca;
            float c2 = 2.0f * ca * ca - 1.0f;
            bufA[(10 + k) * BP + p] = s2;
            bufA[(15 + k) * BP + p] = c2;
            sa = s2; ca = c2;
        }
    }
    __syncthreads();

    int og = tid >> 6;
    int pl = tid & 63;

    k1_layer(bufA, bufB, sw1, sb1, og, pl);
    __syncthreads();
    k1_layer(bufB, bufA, sw2, sb2, og, pl);
    __syncthreads();

    {
        int ob = og * 10;
        u64 acc[4][5];
#pragma unroll
        for (int ip = 0; ip < 4; ip++)
#pragma unroll
            for (int j = 0; j < 5; j++)
                acc[ip][j] = pk2(sb3[ob + 2*j], sb3[ob + 2*j + 1]);
#pragma unroll 4
        for (int i = 0; i < 20; i++) {
            u64 wv[5];
#pragma unroll
            for (int j = 0; j < 5; j++)
                wv[j] = *(const u64*)&sw3[i * 20 + ob + 2 * j];
#pragma unroll
            for (int ip = 0; ip < 4; ip++) {
                float e = bufA[i * BP + pl + 64 * ip];
                u64 ed = pk2(e, e);
#pragma unroll
                for (int j = 0; j < 5; j++) fma2p(acc[ip][j], ed, wv[j]);
            }
        }
#pragma unroll
        for (int ip = 0; ip < 4; ip++) {
            int n = n0 + pl + 64 * ip;
            if (n < NPTS) {
#pragma unroll
                for (int j = 0; j < 5; j++) {
                    float a0, a1;
                    upk2(acc[ip][j], a0, a1);
                    int i0 = (s * C1_ + ob + 2*j) * NPTS + n;
                    __nv_bfloat16 h0 = __float2bfloat16(a0);
                    __nv_bfloat16 h1 = __float2bfloat16(a1);
                    g_f1hi[i0]        = h0;
                    g_f1lo[i0]        = __float2bfloat16(a0 - __bfloat162float(h0));
                    g_f1hi[i0 + NPTS] = h1;
                    g_f1lo[i0 + NPTS] = __float2bfloat16(a1 - __bfloat162float(h1));
                }
            }
        }
    }
}

// ---------------- K2: g_z1[sc][b] = filt1 . data via WMMA bf16 error-split --------
// 80 blocks x 256 thr (8 warps). Warp w owns rows sc0+16w..+15, all 4 b-tiles.
// D chunks (64x64 hi/lo) staged in smem; A fragments loaded from global.
// acc += Fhi*Dhi + Fhi*Dlo + Flo*Dhi  (bf16 split, err ~2^-17).
#define KCH2 64

__global__ __launch_bounds__(256) void k2_wmma()
{
    __shared__ __align__(16) __nv_bfloat16 Dh[64 * KCH2];
    __shared__ __align__(16) __nv_bfloat16 Dl[64 * KCH2];

    int tid = threadIdx.x;
    int wid = tid >> 5;
    int sc0 = blockIdx.x * 128;
    int rowbase = sc0 + wid * 16;

    nvcuda::wmma::fragment<nvcuda::wmma::accumulator, 16, 16, 16, float> acc[4];
#pragma unroll
    for (int t = 0; t < 4; t++) nvcuda::wmma::fill_fragment(acc[t], 0.0f);

    for (int ch = 0; ch < 25; ch++) {
        int kb = ch * KCH2;
        __syncthreads();
        for (int i = tid; i < 512; i += 256) {
            int b = i >> 3;
            int c = i & 7;
            ((uint4*)Dh)[i] = *(const uint4*)&g_dhi[(size_t)b * NPTS + kb + c * 8];
            ((uint4*)Dl)[i] = *(const uint4*)&g_dlo[(size_t)b * NPTS + kb + c * 8];
        }
        __syncthreads();

#pragma unroll
        for (int ks = 0; ks < 4; ks++) {
            nvcuda::wmma::fragment<nvcuda::wmma::matrix_a, 16, 16, 16,
                                   __nv_bfloat16, nvcuda::wmma::row_major> fah, fal;
            const __nv_bfloat16* pa = g_f1hi + (size_t)rowbase * NPTS + kb + ks * 16;
            const __nv_bfloat16* pl = g_f1lo + (size_t)rowbase * NPTS + kb + ks * 16;
            nvcuda::wmma::load_matrix_sync(fah, pa, NPTS);
            nvcuda::wmma::load_matrix_sync(fal, pl, NPTS);
#pragma unroll
            for (int nt = 0; nt < 4; nt++) {
                nvcuda::wmma::fragment<nvcuda::wmma::matrix_b, 16, 16, 16,
                                       __nv_bfloat16, nvcuda::wmma::col_major> fbh, fbl;
                nvcuda::wmma::load_matrix_sync(fbh, Dh + nt * 16 * KCH2 + ks * 16, KCH2);
                nvcuda::wmma::load_matrix_sync(fbl, Dl + nt * 16 * KCH2 + ks * 16, KCH2);
                nvcuda::wmma::mma_sync(acc[nt], fah, fbh, acc[nt]);
                nvcuda::wmma::mma_sync(acc[nt], fah, fbl, acc[nt]);
                nvcuda::wmma::mma_sync(acc[nt], fal, fbh, acc[nt]);
            }
        }
    }

#pragma unroll
    for (int nt = 0; nt < 4; nt++)
        nvcuda::wmma::store_matrix_sync(g_z1 + (size_t)rowbase * B_ + nt * 16,
                                        acc[nt], B_, nvcuda::wmma::mem_row_major);
}

// ---------------- K3a: h2[s,:] = silu(embed(v0[s]) @ s_w1 + s_b1) -----------------
__global__ __launch_bounds__(128) void k3a_h2(const float* __restrict__ v0,
                                              const float* __restrict__ s_w1,
                                              const float* __restrict__ s_b1)
{
    __shared__ float e[80];
    int s = blockIdx.x, tid = threadIdx.x;
    if (tid < 80) {
        int d = tid / 10, kk = tid % 10;
        float v = v0[s * 8 + d];
        float f = (float)(1 << (kk % 5));
        e[tid] = (kk < 5) ? __sinf(v * f) : __cosf(v * f);
    }
    __syncthreads();
    float a = s_b1[tid];
#pragma unroll 8
    for (int k = 0; k < 80; k++) a += e[k] * s_w1[k * W_ + tid];
    g_h2[s * W_ + tid] = silu_f(a);
}

// ---------------- KG: g_G[k,cb] += sum over 32 s of h2e[s,k] * silu(z1/N)[s,cb] ---
__global__ __launch_bounds__(256) void kG_contract()
{
    __shared__ float h2s[32 * 129];
    __shared__ float z1s[32 * 81];
    int cb0 = blockIdx.x * 80;
    int s0  = blockIdx.y * 32;
    int tid = threadIdx.x;

    for (int i = tid; i < 32 * 32; i += 256) {
        int r = i >> 5, k4 = i & 31;
        float4 v = *(const float4*)&g_h2[(s0 + r) * W_ + 4 * k4];
        h2s[r * 129 + 4 * k4 + 0] = v.x;
        h2s[r * 129 + 4 * k4 + 1] = v.y;
        h2s[r * 129 + 4 * k4 + 2] = v.z;
        h2s[r * 129 + 4 * k4 + 3] = v.w;
    }
    if (tid < 32) h2s[tid * 129 + 128] = 1.0f;

    for (int i = tid; i < 32 * 20; i += 256) {
        int r = i / 20, c4 = i - r * 20;
        float4 a = *(const float4*)&g_z1[(s0 + r) * 1280 + cb0 + 4 * c4];
        float* zr = &z1s[r * 81 + 4 * c4];
        zr[0] = silu_f(a.x * (1.0f / (float)NPTS));
        zr[1] = silu_f(a.y * (1.0f / (float)NPTS));
        zr[2] = silu_f(a.z * (1.0f / (float)NPTS));
        zr[3] = silu_f(a.w * (1.0f / (float)NPTS));
    }
    __syncthreads();

    int kq  = tid & 15;
    int cbq = tid >> 4;

    float acc[9][5];
#pragma unroll
    for (int j = 0; j < 9; j++)
#pragma unroll
        for (int i = 0; i < 5; i++) acc[j][i] = 0.0f;

    for (int sl = 0; sl < 32; sl++) {
        float h[9];
#pragma unroll
        for (int j = 0; j < 8; j++) h[j] = h2s[sl * 129 + kq + 16 * j];
        h[8] = h2s[sl * 129 + 128];
        float z[5];
#pragma unroll
        for (int i = 0; i < 5; i++) z[i] = z1s[sl * 81 + cbq + 16 * i];
#pragma unroll
        for (int j = 0; j < 9; j++)
#pragma unroll
            for (int i = 0; i < 5; i++) acc[j][i] += h[j] * z[i];
    }

#pragma unroll
    for (int j = 0; j < 9; j++) {
        int k = kq + 16 * j;
        if (j < 8 || kq == 0) {
#pragma unroll
            for (int i = 0; i < 5; i++)
                atomicAdd(&g_G[k * 1280 + cb0 + cbq + 16 * i], acc[j][i]);
        }
    }
}

// ---------------- KZ: g_z2[b][w] += sum over 30 kc of G[k,cb] * W2ext -------------
__global__ __launch_bounds__(256) void kZ_out(const float* __restrict__ s_w2,
                                              const float* __restrict__ s_b2)
{
    __shared__ float Gt[30 * 64];
    __shared__ float Wt[30 * 128];
    int kc0 = blockIdx.x * 30;
    int tid = threadIdx.x;

    for (int i = tid; i < 30 * 32; i += 256) {
        int kcl = i >> 5, w4 = i & 31;
        int kc = kc0 + kcl, k = kc / 20, c = kc - k * 20;
        float4 v = (k < 128) ? *(const float4*)&s_w2[k * 2560 + c * 128 + 4 * w4]
                             : *(const float4*)&s_b2[c * 128 + 4 * w4];
        *(float4*)&Wt[kcl * 128 + 4 * w4] = v;
    }
    for (int i = tid; i < 30 * 16; i += 256) {
        int kcl = i >> 4, b4 = i & 15;
        int kc = kc0 + kcl, k = kc / 20, c = kc - k * 20;
        float4 a = *(const float4*)&g_G[k * 1280 + c * 64 + 4 * b4];
        *(float4*)&Gt[kcl * 64 + 4 * b4] = a;
    }
    __syncthreads();

    int wq = tid & 15;
    int bq = tid >> 4;
    float acc[4][8];
#pragma unroll
    for (int i = 0; i < 4; i++)
#pragma unroll
        for (int m = 0; m < 8; m++) acc[i][m] = 0.0f;

    for (int kcl = 0; kcl < 30; kcl++) {
        float g[4];
#pragma unroll
        for (int i = 0; i < 4; i++) g[i] = Gt[kcl * 64 + bq + 16 * i];
#pragma unroll
        for (int m = 0; m < 8; m++) {
            float w = Wt[kcl * 128 + wq + 16 * m];
#pragma unroll
            for (int i = 0; i < 4; i++) acc[i][m] += g[i] * w;
        }
    }
#pragma unroll
    for (int i = 0; i < 4; i++)
#pragma unroll
        for (int m = 0; m < 8; m++)
            atomicAdd(&g_z2[(bq + 16 * i) * W_ + wq + 16 * m], acc[i][m]);
}

// ---------------- K5: residual MLP + pool -----------------------------------------
__global__ __launch_bounds__(128) void k5_head(const float* __restrict__ fc1_w,
                                               const float* __restrict__ fc1_b,
                                               const float* __restrict__ fc2_w,
                                               const float* __restrict__ fc2_b,
                                               const float* __restrict__ pool_w,
                                               const float* __restrict__ pool_b,
                                               float* __restrict__ out)
{
    __shared__ float zs[128], r1[128], r2[128];
    int b = blockIdx.x, w = threadIdx.x;

    float a = g_z2[b * W_ + w] * (1.0f / (float)S_);
    zs[w] = a;
    __syncthreads();

    float u = fc1_b[w];
#pragma unroll 8
    for (int k = 0; k < 128; k++) u += zs[k] * fc1_w[k * W_ + w];
    r1[w] = silu_f(u) + zs[w];
    __syncthreads();

    u = fc2_b[w];
#pragma unroll 8
    for (int k = 0; k < 128; k++) u += r1[k] * fc2_w[k * W_ + w];
    r2[w] = silu_f(u) + r1[w];
    __syncthreads();

    if (w < 10) {
        float o = pool_b[w];
        for (int k = 0; k < 128; k++) o += r2[k] * pool_w[k * 10 + w];
        out[b * 10 + w] = o;
    }
}

// ---------------- host launcher ---------------------------------------------------
extern "C" void kernel_launch(void* const* d_in, const int* in_sizes, int n_in,
                              void* d_out, int out_size)
{
    const float* data   = (const float*)d_in[0];
    const float* v0     = (const float*)d_in[1];
    const float* v_last = (const float*)d_in[2];
    const float* fl_w1  = (const float*)d_in[3];
    const float* fl_b1  = (const float*)d_in[4];
    const float* fl_w2  = (const float*)d_in[5];
    const float* fl_b2  = (const float*)d_in[6];
    const float* fl_w3  = (const float*)d_in[7];
    const float* fl_b3  = (const float*)d_in[8];
    const float* s_w1   = (const float*)d_in[9];
    const float* s_b1   = (const float*)d_in[10];
    const float* s_w2   = (const float*)d_in[11];
    const float* s_b2   = (const float*)d_in[12];
    const float* fc1_w  = (const float*)d_in[13];
    const float* fc1_b  = (const float*)d_in[14];
    const float* fc2_w  = (const float*)d_in[15];
    const float* fc2_b  = (const float*)d_in[16];
    const float* pool_w = (const float*)d_in[17];
    const float* pool_b = (const float*)d_in[18];

    kzero<<<162, 256>>>();
    kdata<<<400, 256>>>(data);
    k3a_h2<<<S_, 128>>>(v0, s_w1, s_b1);
    k1_filt1<<<dim3(7, S_), 128>>>(v_last, fl_w1, fl_b1, fl_w2, fl_b2, fl_w3, fl_b3);
    k2_wmma<<<80, 256>>>();
    kG_contract<<<dim3(16, GSPLIT), 256>>>();
    kZ_out<<<ZSPLIT, 256>>>(s_w2, s_b2);
    k5_head<<<B_, 128>>>(fc1_w, fc1_b, fc2_w, fc2_b, pool_w, pool_b, (float*)d_out);
}

// round 17
// speedup vs baseline: 1.6012x; 1.6012x over previous
#include <cuda_runtime.h>
#include <cuda_bf16.h>
#include <mma.h>
#include <math.h>

#define B_     64
#define NSIDE  40
#define NPTS   1600
#define S_     512
#define C1_    20
#define W_     128
#define SCN    10240
#define GSPLIT 16
#define ZSPLIT 86

typedef unsigned long long u64;

// ---------------- scratch (device globals; no runtime allocation) ----------------
__device__ __align__(16) __nv_bfloat16 g_f1hi[SCN * NPTS];
__device__ __align__(16) __nv_bfloat16 g_f1lo[SCN * NPTS];
__device__ __align__(16) __nv_bfloat16 g_dhi [B_ * NPTS];
__device__ __align__(16) __nv_bfloat16 g_dlo [B_ * NPTS];
__device__ __align__(16) float g_z1  [SCN * B_];
__device__ __align__(16) float g_h2  [S_ * W_];
__device__ __align__(16) float g_G   [129 * 1280];
__device__ __align__(16) float g_z2  [B_ * W_];

// ---------------- f32x2 helpers ---------------------------------------------------
__device__ __forceinline__ u64 pk2(float lo, float hi) {
    u64 r;
    asm("mov.b64 %0, {%1, %2};" : "=l"(r) : "f"(lo), "f"(hi));
    return r;
}
__device__ __forceinline__ void upk2(u64 v, float& lo, float& hi) {
    asm("mov.b64 {%0, %1}, %2;" : "=f"(lo), "=f"(hi) : "l"(v));
}
__device__ __forceinline__ void fma2p(u64& d, u64 a, u64 b) {
    asm("fma.rn.f32x2 %0, %1, %2, %0;" : "+l"(d) : "l"(a), "l"(b));
}

__device__ __forceinline__ float silu_f(float x) { return x / (1.0f + __expf(-x)); }
__device__ __forceinline__ float silu_t(float x) {
    float t;
    asm("tanh.approx.f32 %0, %1;" : "=f"(t) : "f"(0.5f * x));
    return 0.5f * x * (1.0f + t);
}

// ---------------- K0: zero atomic accumulators ------------------------------------
__global__ __launch_bounds__(256) void kzero()
{
    int i = blockIdx.x * 256 + threadIdx.x;
    float4 z = make_float4(0.f, 0.f, 0.f, 0.f);
    ((float4*)g_z1)[i] = z;
    if (i < 129 * 1280 / 4) ((float4*)g_G)[i] = z;
    if (i < B_ * W_ / 4)    ((float4*)g_z2)[i] = z;
}

// ---------------- Kdata: split data into bf16 hi/lo -------------------------------
__global__ __launch_bounds__(256) void kdata(const float* __restrict__ data)
{
    int i = blockIdx.x * 256 + threadIdx.x;
    if (i < B_ * NPTS) {
        float v = data[i];
        __nv_bfloat16 h = __float2bfloat16(v);
        g_dhi[i] = h;
        g_dlo[i] = __float2bfloat16(v - __bfloat162float(h));
    }
}

// ---------------- K1: filt1 hi/lo bf16 = MLP(embed(projective coords)) ------------
#define BP 264

__device__ __forceinline__ void k1_layer(const float* in, float* out,
                                         const float* w, const float* bias,
                                         int og, int pl)
{
    int ob = og * 10;
    u64 acc[4][5];
#pragma unroll
    for (int ip = 0; ip < 4; ip++)
#pragma unroll
        for (int j = 0; j < 5; j++)
            acc[ip][j] = pk2(bias[ob + 2*j], bias[ob + 2*j + 1]);
#pragma unroll 4
    for (int i = 0; i < 20; i++) {
        u64 wv[5];
#pragma unroll
        for (int j = 0; j < 5; j++)
            wv[j] = *(const u64*)&w[i * 20 + ob + 2 * j];
#pragma unroll
        for (int ip = 0; ip < 4; ip++) {
            float e = in[i * BP + pl + 64 * ip];
            u64 ed = pk2(e, e);
#pragma unroll
            for (int j = 0; j < 5; j++) fma2p(acc[ip][j], ed, wv[j]);
        }
    }
#pragma unroll
    for (int ip = 0; ip < 4; ip++)
#pragma unroll
        for (int j = 0; j < 5; j++) {
            float a0, a1;
            upk2(acc[ip][j], a0, a1);
            out[(ob + 2*j)     * BP + pl + 64 * ip] = silu_t(a0);
            out[(ob + 2*j + 1) * BP + pl + 64 * ip] = silu_t(a1);
        }
}

__global__ __launch_bounds__(128) void k1_filt1(
    const float* __restrict__ v_last,
    const float* __restrict__ fw1, const float* __restrict__ fb1,
    const float* __restrict__ fw2, const float* __restrict__ fb2,
    const float* __restrict__ fw3, const float* __restrict__ fb3)
{
    __shared__ __align__(16) float sw1[400], sw2[400], sw3[400];
    __shared__ float sb1[20], sb2[20], sb3[20];
    __shared__ __align__(16) float bufA[20 * BP], bufB[20 * BP];

    int s   = blockIdx.y;
    int n0  = blockIdx.x * 256;
    int tid = threadIdx.x;

    for (int i = tid; i < 400; i += 128) {
        sw1[i] = fw1[i];
        sw2[i] = fw2[i];
        sw3[i] = fw3[i];
    }
    if (tid < 20) {
        sb1[tid] = fb1[tid];
        sb2[tid] = fb2[tid];
        sb3[tid] = fb3[tid];
    }

    float v[8];
#pragma unroll
    for (int i = 0; i < 8; i++) v[i] = 0.1f * __ldg(&v_last[s * 8 + i]);

#pragma unroll
    for (int q = 0; q < 2; q++) {
        int p = tid + q * 128;
        int n = n0 + p;
        int ic = n / NSIDE, jc = n - ic * NSIDE;
        float x = -1.0f + (2.0f / 39.0f) * (float)ic;
        float y = -1.0f + (2.0f / 39.0f) * (float)jc;
        float y0 = (1.0f + v[0]) * x + v[1] * y + v[2];
        float y1 = v[3] * x + (1.0f + v[4]) * y + v[5];
        float y2 = v[6] * x + v[7] * y + 1.0f;
        float inv = __frcp_rn(y2);
        float t0 = y0 * inv, t1 = y1 * inv;

        float sa, ca;
        __sincosf(t0, &sa, &ca);
        bufA[0 * BP + p] = sa;
        bufA[5 * BP + p] = ca;
#pragma unroll
        for (int k = 1; k < 5; k++) {
            float s2 = 2.0f * sa * ca;
            float c2 = 2.0f * ca * ca - 1.0f;
            bufA[k * BP + p] = s2;
            bufA[(5 + k) * BP + p] = c2;
            sa = s2; ca = c2;
        }
        __sincosf(t1, &sa, &ca);
        bufA[10 * BP + p] = sa;
        bufA[15 * BP + p] = ca;
#pragma unroll
        for (int k = 1; k < 5; k++) {
            float s2 = 2.0f * sa * ca;
            float c2 = 2.0f * ca * ca - 1.0f;
            bufA[(10 + k) * BP + p] = s2;
            bufA[(15 + k) * BP + p] = c2;
            sa = s2; ca = c2;
        }
    }
    __syncthreads();

    int og = tid >> 6;
    int pl = tid & 63;

    k1_layer(bufA, bufB, sw1, sb1, og, pl);
    __syncthreads();
    k1_layer(bufB, bufA, sw2, sb2, og, pl);
    __syncthreads();

    {
        int ob = og * 10;
        u64 acc[4][5];
#pragma unroll
        for (int ip = 0; ip < 4; ip++)
#pragma unroll
            for (int j = 0; j < 5; j++)
                acc[ip][j] = pk2(sb3[ob + 2*j], sb3[ob + 2*j + 1]);
#pragma unroll 4
        for (int i = 0; i < 20; i++) {
            u64 wv[5];
#pragma unroll
            for (int j = 0; j < 5; j++)
                wv[j] = *(const u64*)&sw3[i * 20 + ob + 2 * j];
#pragma unroll
            for (int ip = 0; ip < 4; ip++) {
                float e = bufA[i * BP + pl + 64 * ip];
                u64 ed = pk2(e, e);
#pragma unroll
                for (int j = 0; j < 5; j++) fma2p(acc[ip][j], ed, wv[j]);
            }
        }
#pragma unroll
        for (int ip = 0; ip < 4; ip++) {
            int n = n0 + pl + 64 * ip;
            if (n < NPTS) {
#pragma unroll
                for (int j = 0; j < 5; j++) {
                    float a0, a1;
                    upk2(acc[ip][j], a0, a1);
                    int i0 = (s * C1_ + ob + 2*j) * NPTS + n;
                    __nv_bfloat16 h0 = __float2bfloat16(a0);
                    __nv_bfloat16 h1 = __float2bfloat16(a1);
                    g_f1hi[i0]        = h0;
                    g_f1lo[i0]        = __float2bfloat16(a0 - __bfloat162float(h0));
                    g_f1hi[i0 + NPTS] = h1;
                    g_f1lo[i0 + NPTS] = __float2bfloat16(a1 - __bfloat162float(h1));
                }
            }
        }
    }
}

// ---------------- K2: g_z1[sc][b] += filt1 . data via WMMA bf16 error-split -------
// grid (80 sc-tiles x 5 k-splits), 256 thr (8 warps). Warp w owns rows sc0+16w..+15.
// Per block K=320 in 10 chunks of 32; A and D tiles staged in smem (coalesced).
// acc += Fhi*Dhi + Fhi*Dlo + Flo*Dhi. Epilogue: fragment -> smem -> atomicAdd.
#define KC2 32

__global__ __launch_bounds__(256) void k2_wmma()
{
    __shared__ __align__(16) __nv_bfloat16 Ah[128 * KC2];
    __shared__ __align__(16) __nv_bfloat16 Al[128 * KC2];
    __shared__ __align__(16) __nv_bfloat16 Dh2[64 * KC2];
    __shared__ __align__(16) __nv_bfloat16 Dl2[64 * KC2];
    __shared__ __align__(16) float zsc[8 * 256];

    int tid = threadIdx.x;
    int wid = tid >> 5;
    int lane = tid & 31;
    int sc0 = blockIdx.x * 128;
    int kb0 = blockIdx.y * 320;
    int rowbase = sc0 + wid * 16;

    nvcuda::wmma::fragment<nvcuda::wmma::accumulator, 16, 16, 16, float> acc[4];
#pragma unroll
    for (int t = 0; t < 4; t++) nvcuda::wmma::fill_fragment(acc[t], 0.0f);

    for (int ch = 0; ch < 10; ch++) {
        int kb = kb0 + ch * KC2;
        __syncthreads();
        // A tiles: 128 rows x 32 k = 512 uint4 each (4 uint4 per row)
        for (int i = tid; i < 512; i += 256) {
            int r = i >> 2;
            int c = i & 3;
            ((uint4*)Ah)[i] = *(const uint4*)&g_f1hi[(size_t)(sc0 + r) * NPTS + kb + c * 8];
            ((uint4*)Al)[i] = *(const uint4*)&g_f1lo[(size_t)(sc0 + r) * NPTS + kb + c * 8];
        }
        // D tiles: 64 rows x 32 k = 256 uint4 each
        for (int i = tid; i < 256; i += 256) {
            int r = i >> 2;
            int c = i & 3;
            ((uint4*)Dh2)[i] = *(const uint4*)&g_dhi[(size_t)r * NPTS + kb + c * 8];
            ((uint4*)Dl2)[i] = *(const uint4*)&g_dlo[(size_t)r * NPTS + kb + c * 8];
        }
        __syncthreads();

#pragma unroll
        for (int ks = 0; ks < 2; ks++) {
            nvcuda::wmma::fragment<nvcuda::wmma::matrix_a, 16, 16, 16,
                                   __nv_bfloat16, nvcuda::wmma::row_major> fah, fal;
            nvcuda::wmma::load_matrix_sync(fah, Ah + wid * 16 * KC2 + ks * 16, KC2);
            nvcuda::wmma::load_matrix_sync(fal, Al + wid * 16 * KC2 + ks * 16, KC2);
#pragma unroll
            for (int nt = 0; nt < 4; nt++) {
                nvcuda::wmma::fragment<nvcuda::wmma::matrix_b, 16, 16, 16,
                                       __nv_bfloat16, nvcuda::wmma::col_major> fbh, fbl;
                nvcuda::wmma::load_matrix_sync(fbh, Dh2 + nt * 16 * KC2 + ks * 16, KC2);
                nvcuda::wmma::load_matrix_sync(fbl, Dl2 + nt * 16 * KC2 + ks * 16, KC2);
                nvcuda::wmma::mma_sync(acc[nt], fah, fbh, acc[nt]);
                nvcuda::wmma::mma_sync(acc[nt], fah, fbl, acc[nt]);
                nvcuda::wmma::mma_sync(acc[nt], fal, fbh, acc[nt]);
            }
        }
    }

    // epilogue: fragment -> per-warp smem scratch -> atomicAdd into g_z1
#pragma unroll
    for (int nt = 0; nt < 4; nt++) {
        nvcuda::wmma::store_matrix_sync(zsc + wid * 256, acc[nt], 16,
                                        nvcuda::wmma::mem_row_major);
        __syncwarp();
#pragma unroll
        for (int e = 0; e < 8; e++) {
            int idx = lane + e * 32;
            int r = idx >> 4;
            int c = idx & 15;
            atomicAdd(&g_z1[(size_t)(rowbase + r) * B_ + nt * 16 + c],
                      zsc[wid * 256 + r * 16 + c]);
        }
        __syncwarp();
    }
}

// ---------------- K3a: h2[s,:] = silu(embed(v0[s]) @ s_w1 + s_b1) -----------------
__global__ __launch_bounds__(128) void k3a_h2(const float* __restrict__ v0,
                                              const float* __restrict__ s_w1,
                                              const float* __restrict__ s_b1)
{
    __shared__ float e[80];
    int s = blockIdx.x, tid = threadIdx.x;
    if (tid < 80) {
        int d = tid / 10, kk = tid % 10;
        float v = v0[s * 8 + d];
        float f = (float)(1 << (kk % 5));
        e[tid] = (kk < 5) ? __sinf(v * f) : __cosf(v * f);
    }
    __syncthreads();
    float a = s_b1[tid];
#pragma unroll 8
    for (int k = 0; k < 80; k++) a += e[k] * s_w1[k * W_ + tid];
    g_h2[s * W_ + tid] = silu_f(a);
}

// ---------------- KG: g_G[k,cb] += sum over 32 s of h2e[s,k] * silu(z1/N)[s,cb] ---
__global__ __launch_bounds__(256) void kG_contract()
{
    __shared__ float h2s[32 * 129];
    __shared__ float z1s[32 * 81];
    int cb0 = blockIdx.x * 80;
    int s0  = blockIdx.y * 32;
    int tid = threadIdx.x;

    for (int i = tid; i < 32 * 32; i += 256) {
        int r = i >> 5, k4 = i & 31;
        float4 v = *(const float4*)&g_h2[(s0 + r) * W_ + 4 * k4];
        h2s[r * 129 + 4 * k4 + 0] = v.x;
        h2s[r * 129 + 4 * k4 + 1] = v.y;
        h2s[r * 129 + 4 * k4 + 2] = v.z;
        h2s[r * 129 + 4 * k4 + 3] = v.w;
    }
    if (tid < 32) h2s[tid * 129 + 128] = 1.0f;

    for (int i = tid; i < 32 * 20; i += 256) {
        int r = i / 20, c4 = i - r * 20;
        float4 a = *(const float4*)&g_z1[(s0 + r) * 1280 + cb0 + 4 * c4];
        float* zr = &z1s[r * 81 + 4 * c4];
        zr[0] = silu_f(a.x * (1.0f / (float)NPTS));
        zr[1] = silu_f(a.y * (1.0f / (float)NPTS));
        zr[2] = silu_f(a.z * (1.0f / (float)NPTS));
        zr[3] = silu_f(a.w * (1.0f / (float)NPTS));
    }
    __syncthreads();

    int kq  = tid & 15;
    int cbq = tid >> 4;

    float acc[9][5];
#pragma unroll
    for (int j = 0; j < 9; j++)
#pragma unroll
        for (int i = 0; i < 5; i++) acc[j][i] = 0.0f;

    for (int sl = 0; sl < 32; sl++) {
        float h[9];
#pragma unroll
        for (int j = 0; j < 8; j++) h[j] = h2s[sl * 129 + kq + 16 * j];
        h[8] = h2s[sl * 129 + 128];
        float z[5];
#pragma unroll
        for (int i = 0; i < 5; i++) z[i] = z1s[sl * 81 + cbq + 16 * i];
#pragma unroll
        for (int j = 0; j < 9; j++)
#pragma unroll
            for (int i = 0; i < 5; i++) acc[j][i] += h[j] * z[i];
    }

#pragma unroll
    for (int j = 0; j < 9; j++) {
        int k = kq + 16 * j;
        if (j < 8 || kq == 0) {
#pragma unroll
            for (int i = 0; i < 5; i++)
                atomicAdd(&g_G[k * 1280 + cb0 + cbq + 16 * i], acc[j][i]);
        }
    }
}

// ---------------- KZ: g_z2[b][w] += sum over 30 kc of G[k,cb] * W2ext -------------
__global__ __launch_bounds__(256) void kZ_out(const float* __restrict__ s_w2,
                                              const float* __restrict__ s_b2)
{
    __shared__ float Gt[30 * 64];
    __shared__ float Wt[30 * 128];
    int kc0 = blockIdx.x * 30;
    int tid = threadIdx.x;

    for (int i = tid; i < 30 * 32; i += 256) {
        int kcl = i >> 5, w4 = i & 31;
        int kc = kc0 + kcl, k = kc / 20, c = kc - k * 20;
        float4 v = (k < 128) ? *(const float4*)&s_w2[k * 2560 + c * 128 + 4 * w4]
                             : *(const float4*)&s_b2[c * 128 + 4 * w4];
        *(float4*)&Wt[kcl * 128 + 4 * w4] = v;
    }
    for (int i = tid; i < 30 * 16; i += 256) {
        int kcl = i >> 4, b4 = i & 15;
        int kc = kc0 + kcl, k = kc / 20, c = kc - k * 20;
        float4 a = *(const float4*)&g_G[k * 1280 + c * 64 + 4 * b4];
        *(float4*)&Gt[kcl * 64 + 4 * b4] = a;
    }
    __syncthreads();

    int wq = tid & 15;
    int bq = tid >> 4;
    float acc[4][8];
#pragma unroll
    for (int i = 0; i < 4; i++)
#pragma unroll
        for (int m = 0; m < 8; m++) acc[i][m] = 0.0f;

    for (int kcl = 0; kcl < 30; kcl++) {
        float g[4];
#pragma unroll
        for (int i = 0; i < 4; i++) g[i] = Gt[kcl * 64 + bq + 16 * i];
#pragma unroll
        for (int m = 0; m < 8; m++) {
            float w = Wt[kcl * 128 + wq + 16 * m];
#pragma unroll
            for (int i = 0; i < 4; i++) acc[i][m] += g[i] * w;
        }
    }
#pragma unroll
    for (int i = 0; i < 4; i++)
#pragma unroll
        for (int m = 0; m < 8; m++)
            atomicAdd(&g_z2[(bq + 16 * i) * W_ + wq + 16 * m], acc[i][m]);
}

// ---------------- K5: residual MLP + pool -----------------------------------------
__global__ __launch_bounds__(128) void k5_head(const float* __restrict__ fc1_w,
                                               const float* __restrict__ fc1_b,
                                               const float* __restrict__ fc2_w,
                                               const float* __restrict__ fc2_b,
                                               const float* __restrict__ pool_w,
                                               const float* __restrict__ pool_b,
                                               float* __restrict__ out)
{
    __shared__ float zs[128], r1[128], r2[128];
    int b = blockIdx.x, w = threadIdx.x;

    float a = g_z2[b * W_ + w] * (1.0f / (float)S_);
    zs[w] = a;
    __syncthreads();

    float u = fc1_b[w];
#pragma unroll 8
    for (int k = 0; k < 128; k++) u += zs[k] * fc1_w[k * W_ + w];
    r1[w] = silu_f(u) + zs[w];
    __syncthreads();

    u = fc2_b[w];
#pragma unroll 8
    for (int k = 0; k < 128; k++) u += r1[k] * fc2_w[k * W_ + w];
    r2[w] = silu_f(u) + r1[w];
    __syncthreads();

    if (w < 10) {
        float o = pool_b[w];
        for (int k = 0; k < 128; k++) o += r2[k] * pool_w[k * 10 + w];
        out[b * 10 + w] = o;
    }
}

// ---------------- host launcher ---------------------------------------------------
extern "C" void kernel_launch(void* const* d_in, const int* in_sizes, int n_in,
                              void* d_out, int out_size)
{
    const float* data   = (const float*)d_in[0];
    const float* v0     = (const float*)d_in[1];
    const float* v_last = (const float*)d_in[2];
    const float* fl_w1  = (const float*)d_in[3];
    const float* fl_b1  = (const float*)d_in[4];
    const float* fl_w2  = (const float*)d_in[5];
    const float* fl_b2  = (const float*)d_in[6];
    const float* fl_w3  = (const float*)d_in[7];
    const float* fl_b3  = (const float*)d_in[8];
    const float* s_w1   = (const float*)d_in[9];
    const float* s_b1   = (const float*)d_in[10];
    const float* s_w2   = (const float*)d_in[11];
    const float* s_b2   = (const float*)d_in[12];
    const float* fc1_w  = (const float*)d_in[13];
    const float* fc1_b  = (const float*)d_in[14];
    const float* fc2_w  = (const float*)d_in[15];
    const float* fc2_b  = (const float*)d_in[16];
    const float* pool_w = (const float*)d_in[17];
    const float* pool_b = (const float*)d_in[18];

    kzero<<<640, 256>>>();
    kdata<<<400, 256>>>(data);
    k3a_h2<<<S_, 128>>>(v0, s_w1, s_b1);
    k1_filt1<<<dim3(7, S_), 128>>>(v_last, fl_w1, fl_b1, fl_w2, fl_b2, fl_w3, fl_b3);
    k2_wmma<<<dim3(80, 5), 256>>>();
    kG_contract<<<dim3(16, GSPLIT), 256>>>();
    kZ_out<<<ZSPLIT, 256>>>(s_w2, s_b2);
    k5_head<<<B_, 128>>>(fc1_w, fc1_b, fc2_w, fc2_b, pool_w, pool_b, (float*)d_out);
}